// round 11
// baseline (speedup 1.0000x reference)
#include <cuda_runtime.h>
#include <cuda_fp16.h>
#include <cstdint>

// ----------------------------------------------------------------------------
// Attention_53944789237811  (round 11: interleaved cp.async prefetch in kg loop)
//   keys    = LayerNorm(Y @ K) * g1 + b1          [B,S,H]
//   queries = LayerNorm(X @ Q) * g2 + b2          [B,S,H]
//   alpha   = softmax(queries @ keys^T / H)       [B,S,S]
//   out     = alpha @ Y                           [B,S,F]
// B=8, S=2048, F=H=1024.
// ----------------------------------------------------------------------------

// ---------------- scratch (device globals; no cudaMalloc allowed) ------------
__device__ __half g_xh      [8ull * 2048 * 1024];   //  32 MB  X (half)
__device__ __half g_yh      [8ull * 2048 * 1024];   //  32 MB  Y (half)
__device__ __half g_kth     [1024ull * 1024];       //   2 MB  K^T
__device__ __half g_qth     [1024ull * 1024];       //   2 MB  Q^T
__device__ __half g_yth     [8ull * 1024 * 2048];   //  32 MB  Y^T
__device__ __half g_keysh   [8ull * 2048 * 1024];   //  32 MB  proj -> LN'd keys
__device__ __half g_queriesh[8ull * 2048 * 1024];   //  32 MB  proj -> LN'd queries
__device__ __half g_alphah  [8ull * 2048 * 2048];   //  64 MB  exp(logits)
__device__ float  g_rowsum  [8ull * 2048];          //  64 KB  softmax denominators

// ---------------- helpers ------------------------------------------------------
__device__ __forceinline__ uint32_t smem_u32(const void* p) {
    uint32_t a;
    asm("{ .reg .u64 t; cvta.to.shared.u64 t, %1; cvt.u32.u64 %0, t; }"
        : "=r"(a) : "l"(p));
    return a;
}

__device__ __forceinline__ void mma_fp16(float* c, const uint32_t* a, const uint32_t* b) {
    asm volatile(
        "mma.sync.aligned.m16n8k16.row.col.f32.f16.f16.f32 "
        "{%0,%1,%2,%3}, {%4,%5,%6,%7}, {%8,%9}, {%0,%1,%2,%3};\n"
        : "+f"(c[0]), "+f"(c[1]), "+f"(c[2]), "+f"(c[3])
        : "r"(a[0]), "r"(a[1]), "r"(a[2]), "r"(a[3]), "r"(b[0]), "r"(b[1]));
}

__device__ __forceinline__ void ldsm4(uint32_t* r, uint32_t addr) {
    asm volatile("ldmatrix.sync.aligned.m8n8.x4.shared.b16 {%0,%1,%2,%3}, [%4];"
                 : "=r"(r[0]), "=r"(r[1]), "=r"(r[2]), "=r"(r[3]) : "r"(addr));
}

__device__ __forceinline__ void cp16(uint32_t dst, const void* src) {
    asm volatile("cp.async.cg.shared.global [%0], [%1], 16;"
                 :: "r"(dst), "l"(src) : "memory");
}
#define CP_COMMIT() asm volatile("cp.async.commit_group;" ::: "memory")

#define SWZ(o) ((o) ^ ((((uint32_t)(o)) >> 3) & 0x70u))

// ---------------- fp16 tensor GEMM ---------------------------------------------
// C = A[M,K] * B[N,K]^T.  CTA tile 128x128, BK=64, 3-stage cp.async, 256 threads,
// warp tile 32x64. Next-stage cp.async interleaved into the kg compute loop so
// LDGSTS issue in the shadow of HMMA instead of bursting at stage start.
// EPI 0: C half (plain convert); blockIdx.z selects pair (A0,B0,C0)/(A1,B1,C1)
// EPI 1: C half = exp(acc/1024), + rowsum  [QK logits]   (z = batch)
// EPI 2: C f32  = acc / rowsum[row]        [PV output]   (z = batch)
#define TILEB  16384
#define STAGEB 32768
#define GSMEM  (3 * STAGEB)   // 96 KB -> 2 CTAs/SM

__device__ __forceinline__ void load_stage(
    const __half* A, const __half* B, int Kd, int row0, int col0, int kk,
    uint32_t abuf, uint32_t bbuf, int tid)
{
#pragma unroll
    for (int i = 0; i < 4; i++) {
        int ch = tid + i * 256;
        int r = ch >> 3, c = ch & 7;
        cp16(abuf + SWZ(r * 128 + c * 16),
             A + (long long)(row0 + r) * Kd + kk + c * 8);
    }
#pragma unroll
    for (int i = 0; i < 4; i++) {
        int ch = tid + i * 256;
        int r = ch >> 3, c = ch & 7;
        cp16(bbuf + SWZ(r * 128 + c * 16),
             B + (long long)(col0 + r) * Kd + kk + c * 8);
    }
    CP_COMMIT();
}

template <int EPI>
__global__ __launch_bounds__(256, 2)
void gemm_h(const __half* __restrict__ A, const __half* __restrict__ B,
            void* __restrict__ Cv,
            const __half* __restrict__ A1, const __half* __restrict__ B1,
            void* __restrict__ C1,
            float* __restrict__ rowsum,
            int M, int N, int Kd,
            long long sA, long long sB, long long sC, long long sR)
{
    extern __shared__ __align__(1024) char smem[];
    if (EPI == 0) {
        if (blockIdx.z) { A = A1; B = B1; Cv = C1; }
    } else {
        A += (long long)blockIdx.z * sA;
        B += (long long)blockIdx.z * sB;
        rowsum += (long long)blockIdx.z * sR;
    }

    const uint32_t sbase = smem_u32(smem);
    const int tid  = threadIdx.x;
    const int warp = tid >> 5;
    const int lane = tid & 31;
    const int gid  = lane >> 2;
    const int tig  = lane & 3;
    const int warp_m = warp & 3;
    const int warp_n = warp >> 2;
    const int row0 = blockIdx.y * 128;
    const int col0 = blockIdx.x * 128;

    const int l7 = lane & 7;
    uint32_t aoff[2], axm[2];
#pragma unroll
    for (int mt = 0; mt < 2; mt++) {
        int row = warp_m * 32 + mt * 16 + ((lane >> 3) & 1) * 8 + l7;
        aoff[mt] = (uint32_t)row * 128;
        axm[mt]  = (uint32_t)(row & 7) * 16;
    }
    const uint32_t aq = (uint32_t)((lane >> 4) & 1) * 16;
    uint32_t boff[4], bxm[4];
#pragma unroll
    for (int p = 0; p < 4; p++) {
        int row = warp_n * 64 + p * 16 + ((lane >> 4) & 1) * 8 + l7;
        boff[p] = (uint32_t)row * 128;
        bxm[p]  = (uint32_t)(row & 7) * 16;
    }
    const uint32_t bq = (uint32_t)((lane >> 3) & 1) * 16;

    // loader lane constants (for interleaved prefetch)
    const int ldr = tid >> 3;          // row within 32-row chunk group
    const int ldc = (tid & 7) * 16;    // 16B column offset
    const long long arowK = (long long)(row0 + ldr) * Kd + (ldc >> 1); // in halves
    const long long browK = (long long)(col0 + ldr) * Kd + (ldc >> 1);

    float acc[2][8][4];
#pragma unroll
    for (int i = 0; i < 2; i++)
#pragma unroll
        for (int j = 0; j < 8; j++)
#pragma unroll
            for (int l = 0; l < 4; l++) acc[i][j][l] = 0.f;

    const int nst = Kd / 64;

    load_stage(A, B, Kd, row0, col0, 0,  sbase, sbase + TILEB, tid);
    load_stage(A, B, Kd, row0, col0, 64, sbase + STAGEB, sbase + STAGEB + TILEB, tid);

    for (int s = 0; s < nst; s++) {
        if (s + 1 < nst)
            asm volatile("cp.async.wait_group 1;" ::: "memory");
        else
            asm volatile("cp.async.wait_group 0;" ::: "memory");
        __syncthreads();

        const uint32_t abuf = sbase + (s % 3) * STAGEB;
        const uint32_t bbuf = abuf + TILEB;

        const bool pf = (s + 2 < nst);
        const int  tkk = (s + 2) * 64;
        const uint32_t pbase = sbase + ((s + 2) % 3) * STAGEB;
        // swizzled smem target for this thread's chunk row ldr + kg*32
        // (recomputed per kg below; base pieces are lane-constant)

#pragma unroll
        for (int kg = 0; kg < 4; kg++) {
            uint32_t a[2][4], b[4][4];
#pragma unroll
            for (int mt = 0; mt < 2; mt++)
                ldsm4(a[mt], abuf + aoff[mt] + (((uint32_t)kg * 32 + aq) ^ axm[mt]));
#pragma unroll
            for (int p = 0; p < 4; p++)
                ldsm4(b[p], bbuf + boff[p] + (((uint32_t)kg * 32 + bq) ^ bxm[p]));

            // interleaved prefetch: 2 cp.async per kg (A chunk kg, B chunk kg),
            // issued in the shadow of this kg's HMMA chain
            if (pf) {
                int r = ldr + kg * 32;
                uint32_t dsw = SWZ((uint32_t)r * 128 + (uint32_t)ldc);
                cp16(pbase + dsw,         A + (long long)(row0 + r) * Kd + tkk + (ldc >> 1));
                cp16(pbase + TILEB + dsw, B + (long long)(col0 + r) * Kd + tkk + (ldc >> 1));
            }

#pragma unroll
            for (int mt = 0; mt < 2; mt++)
#pragma unroll
                for (int nt = 0; nt < 8; nt++)
                    mma_fp16(acc[mt][nt], a[mt], &b[nt >> 1][(nt & 1) * 2]);
        }
        if (pf) CP_COMMIT();
    }

    // ---- epilogue ----
    if (EPI == 0) {
        __half* C = (__half*)Cv;
#pragma unroll
        for (int mt = 0; mt < 2; mt++) {
            int r = row0 + warp_m * 32 + mt * 16 + gid;
#pragma unroll
            for (int nt = 0; nt < 8; nt++) {
                int c = col0 + warp_n * 64 + nt * 8 + tig * 2;
                *(__half2*)(C + (long long)r * N + c) =
                    __floats2half2_rn(acc[mt][nt][0], acc[mt][nt][1]);
                *(__half2*)(C + (long long)(r + 8) * N + c) =
                    __floats2half2_rn(acc[mt][nt][2], acc[mt][nt][3]);
            }
        }
    } else if (EPI == 1) {
        __half* C = (__half*)Cv + (long long)blockIdx.z * sC;
        const float sc = 1.4426950408889634f / 1024.0f;  // log2(e)/H
#pragma unroll
        for (int mt = 0; mt < 2; mt++) {
            int r = row0 + warp_m * 32 + mt * 16 + gid;
            float rs0 = 0.f, rs1 = 0.f;
#pragma unroll
            for (int nt = 0; nt < 8; nt++) {
                int c = col0 + warp_n * 64 + nt * 8 + tig * 2;
                float p0 = exp2f(acc[mt][nt][0] * sc);
                float p1 = exp2f(acc[mt][nt][1] * sc);
                float p2 = exp2f(acc[mt][nt][2] * sc);
                float p3 = exp2f(acc[mt][nt][3] * sc);
                *(__half2*)(C + (long long)r * N + c)       = __floats2half2_rn(p0, p1);
                *(__half2*)(C + (long long)(r + 8) * N + c) = __floats2half2_rn(p2, p3);
                rs0 += p0 + p1;
                rs1 += p2 + p3;
            }
            rs0 += __shfl_xor_sync(0xffffffffu, rs0, 1);
            rs0 += __shfl_xor_sync(0xffffffffu, rs0, 2);
            rs1 += __shfl_xor_sync(0xffffffffu, rs1, 1);
            rs1 += __shfl_xor_sync(0xffffffffu, rs1, 2);
            if (tig == 0) {
                atomicAdd(&rowsum[r], rs0);
                atomicAdd(&rowsum[r + 8], rs1);
            }
        }
    } else {
        float* C = (float*)Cv + (long long)blockIdx.z * sC;
#pragma unroll
        for (int mt = 0; mt < 2; mt++) {
            int r = row0 + warp_m * 32 + mt * 16 + gid;
            const float i0 = 1.0f / rowsum[r];
            const float i1 = 1.0f / rowsum[r + 8];
#pragma unroll
            for (int nt = 0; nt < 8; nt++) {
                int c = col0 + warp_n * 64 + nt * 8 + tig * 2;
                *(float2*)(C + (long long)r * N + c) =
                    make_float2(acc[mt][nt][0] * i0, acc[mt][nt][1] * i0);
                *(float2*)(C + (long long)(r + 8) * N + c) =
                    make_float2(acc[mt][nt][2] * i1, acc[mt][nt][3] * i1);
            }
        }
    }
}

// ---------------- pre/aux kernels ------------------------------------------------
__global__ __launch_bounds__(256) void cvt_half(const float4* __restrict__ in,
                                                __half2* __restrict__ out, int n4)
{
    int i = blockIdx.x * 256 + threadIdx.x;
    int stride = gridDim.x * 256;
    for (; i < n4; i += stride) {
        float4 v = in[i];
        out[i * 2 + 0] = __floats2half2_rn(v.x, v.y);
        out[i * 2 + 1] = __floats2half2_rn(v.z, v.w);
    }
}

// Read Y once; emit yh (straight half copy) and yth (transposed half).
__global__ __launch_bounds__(256) void cvt_trans_half(
    const float* __restrict__ in, __half* __restrict__ oh, __half* __restrict__ ot,
    int R, int C, long long sIn, long long sOut)
{
    in += (long long)blockIdx.z * sIn;
    oh += (long long)blockIdx.z * sIn;
    ot += (long long)blockIdx.z * sOut;
    __shared__ float t[32][33];
    const int r0 = blockIdx.y * 32, c0 = blockIdx.x * 32;
    const int tx = threadIdx.x & 31, ty = threadIdx.x >> 5;
#pragma unroll
    for (int i = 0; i < 32; i += 8) {
        float v = in[(long long)(r0 + ty + i) * C + c0 + tx];
        t[ty + i][tx] = v;
        oh[(long long)(r0 + ty + i) * C + c0 + tx] = __float2half_rn(v);
    }
    __syncthreads();
#pragma unroll
    for (int i = 0; i < 32; i += 8)
        ot[(long long)(c0 + ty + i) * R + r0 + tx] = __float2half_rn(t[tx][ty + i]);
}

// Transpose BOTH K and Q in one launch (blockIdx.z selects).
__global__ __launch_bounds__(256) void trans2_half(
    const float* __restrict__ in0, __half* __restrict__ out0,
    const float* __restrict__ in1, __half* __restrict__ out1,
    int R, int C)
{
    const float* in = blockIdx.z ? in1 : in0;
    __half* out = blockIdx.z ? out1 : out0;
    __shared__ float t[32][33];
    const int r0 = blockIdx.y * 32, c0 = blockIdx.x * 32;
    const int tx = threadIdx.x & 31, ty = threadIdx.x >> 5;
#pragma unroll
    for (int i = 0; i < 32; i += 8)
        t[ty + i][tx] = in[(long long)(r0 + ty + i) * C + c0 + tx];
    __syncthreads();
#pragma unroll
    for (int i = 0; i < 32; i += 8)
        out[(long long)(c0 + ty + i) * R + r0 + tx] = __float2half_rn(t[tx][ty + i]);
}

// ---------------- fused layernorm (vectorized) + rowsum zeroing -----------------
__global__ __launch_bounds__(128) void layernorm2_kernel(
    __half* __restrict__ d0, const float* __restrict__ ga0, const float* __restrict__ be0,
    __half* __restrict__ d1, const float* __restrict__ ga1, const float* __restrict__ be1,
    float* __restrict__ rowsum)
{
    const int H = 1024;
    __half* row = (blockIdx.y ? d1 : d0) + (long long)blockIdx.x * H;
    const float* gamma = blockIdx.y ? ga1 : ga0;
    const float* beta  = blockIdx.y ? be1 : be0;
    const int t = threadIdx.x;
    const int lane = t & 31, wid = t >> 5;

    if (blockIdx.y == 0 && t == 0) rowsum[blockIdx.x] = 0.f;

    uint4 v = *(uint4*)(row + t * 8);
    __half2 h[4];
    h[0] = *(__half2*)&v.x; h[1] = *(__half2*)&v.y;
    h[2] = *(__half2*)&v.z; h[3] = *(__half2*)&v.w;

    float f[8];
#pragma unroll
    for (int i = 0; i < 4; i++) {
        float2 p = __half22float2(h[i]);
        f[i * 2] = p.x; f[i * 2 + 1] = p.y;
    }
    float s = 0.f, q = 0.f;
#pragma unroll
    for (int i = 0; i < 8; i++) { s += f[i]; q += f[i] * f[i]; }

#pragma unroll
    for (int o = 16; o > 0; o >>= 1) {
        s += __shfl_xor_sync(0xffffffffu, s, o);
        q += __shfl_xor_sync(0xffffffffu, q, o);
    }
    __shared__ float ss[4], sq[4];
    if (lane == 0) { ss[wid] = s; sq[wid] = q; }
    __syncthreads();
    s = ss[0] + ss[1] + ss[2] + ss[3];
    q = sq[0] + sq[1] + sq[2] + sq[3];

    const float mu  = s * (1.f / 1024.f);
    const float var = q * (1.f / 1024.f) - mu * mu;
    const float inv = rsqrtf(var + 1e-5f);

    const int c0 = t * 8;
    float4 g0 = *(const float4*)(gamma + c0);
    float4 g1v = *(const float4*)(gamma + c0 + 4);
    float4 b0 = *(const float4*)(beta + c0);
    float4 b1v = *(const float4*)(beta + c0 + 4);
    const float gg[8] = {g0.x, g0.y, g0.z, g0.w, g1v.x, g1v.y, g1v.z, g1v.w};
    const float bb[8] = {b0.x, b0.y, b0.z, b0.w, b1v.x, b1v.y, b1v.z, b1v.w};

    uint4 o;
    __half2* oh = (__half2*)&o;
#pragma unroll
    for (int i = 0; i < 4; i++) {
        float r0 = (f[i * 2]     - mu) * inv * gg[i * 2]     + bb[i * 2];
        float r1 = (f[i * 2 + 1] - mu) * inv * gg[i * 2 + 1] + bb[i * 2 + 1];
        oh[i] = __floats2half2_rn(r0, r1);
    }
    *(uint4*)(row + t * 8) = o;
}

// ---------------- kernel_launch --------------------------------------------------
extern "C" void kernel_launch(void* const* d_in, const int* in_sizes, int n_in,
                              void* d_out, int out_size)
{
    const float* X  = (const float*)d_in[0];
    const float* Y  = (const float*)d_in[1];
    const float* K  = (const float*)d_in[2];
    const float* Q  = (const float*)d_in[3];
    const float* g1 = (const float*)d_in[4];
    const float* b1 = (const float*)d_in[5];
    const float* g2 = (const float*)d_in[6];
    const float* b2 = (const float*)d_in[7];
    float* out = (float*)d_out;

    __half *xh, *yh, *kth, *qth, *yth, *keysh, *queriesh, *alphah;
    float* rowsum;
    cudaGetSymbolAddress((void**)&xh,       g_xh);
    cudaGetSymbolAddress((void**)&yh,       g_yh);
    cudaGetSymbolAddress((void**)&kth,      g_kth);
    cudaGetSymbolAddress((void**)&qth,      g_qth);
    cudaGetSymbolAddress((void**)&yth,      g_yth);
    cudaGetSymbolAddress((void**)&keysh,    g_keysh);
    cudaGetSymbolAddress((void**)&queriesh, g_queriesh);
    cudaGetSymbolAddress((void**)&alphah,   g_alphah);
    cudaGetSymbolAddress((void**)&rowsum,   g_rowsum);

    cudaFuncSetAttribute(gemm_h<0>, cudaFuncAttributeMaxDynamicSharedMemorySize, GSMEM);
    cudaFuncSetAttribute(gemm_h<1>, cudaFuncAttributeMaxDynamicSharedMemorySize, GSMEM);
    cudaFuncSetAttribute(gemm_h<2>, cudaFuncAttributeMaxDynamicSharedMemorySize, GSMEM);

    const int B = 8, S = 2048, F = 1024, H = 1024;
    const long long nXY = (long long)B * S * F;
    const long long sQK = (long long)S * H;
    const long long sAL = (long long)S * S;
    const long long sY  = (long long)S * F;
    const long long sYT = (long long)F * S;

    // 1) fp16 conversions + transposes
    cvt_half<<<2048, 256>>>((const float4*)X, (__half2*)xh, (int)(nXY / 4));
    cvt_trans_half<<<dim3(F / 32, S / 32, B), 256>>>(Y, yh, yth, S, F, sY, sYT);
    trans2_half<<<dim3(H / 32, F / 32, 2), 256>>>(K, kth, Q, qth, F, H);

    // 2) both projections in ONE launch (z selects pair)
    gemm_h<0><<<dim3(H / 128, (B * S) / 128, 2), 256, GSMEM>>>(
        yh, kth, keysh, xh, qth, queriesh, nullptr,
        B * S, H, F, 0, 0, 0, 0);

    // 3) both layernorms (vectorized) + rowsum zeroing in one launch
    layernorm2_kernel<<<dim3(B * S, 2), 128>>>(keysh, g1, b1, queriesh, g2, b2, rowsum);

    // 4) QK logits + fused exp + row sums: alphah = exp(q.k/H)
    gemm_h<1><<<dim3(S / 128, S / 128, B), 256, GSMEM>>>(
        queriesh, keysh, alphah, nullptr, nullptr, nullptr, rowsum,
        S, S, H, sQK, sQK, sAL, S);

    // 5) PV + fused division: out = (alphah @ yth^T) / rowsum
    gemm_h<2><<<dim3(F / 128, S / 128, B), 256, GSMEM>>>(
        alphah, yth, out, nullptr, nullptr, nullptr, rowsum,
        S, F, S, sAL, sYT, sY, S);
}

// round 12
// speedup vs baseline: 1.0549x; 1.0549x over previous
#include <cuda_runtime.h>
#include <cuda_fp16.h>
#include <cstdint>

// ----------------------------------------------------------------------------
// Attention_53944789237811  (round 12: R10 GEMM revert + merged pre-pass)
//   keys    = LayerNorm(Y @ K) * g1 + b1          [B,S,H]
//   queries = LayerNorm(X @ Q) * g2 + b2          [B,S,H]
//   alpha   = softmax(queries @ keys^T / H)       [B,S,S]
//   out     = alpha @ Y                           [B,S,F]
// B=8, S=2048, F=H=1024.
// ----------------------------------------------------------------------------

// ---------------- scratch (device globals; no cudaMalloc allowed) ------------
__device__ __half g_xh      [8ull * 2048 * 1024];   //  32 MB  X (half)
__device__ __half g_yh      [8ull * 2048 * 1024];   //  32 MB  Y (half)
__device__ __half g_kth     [1024ull * 1024];       //   2 MB  K^T
__device__ __half g_qth     [1024ull * 1024];       //   2 MB  Q^T
__device__ __half g_yth     [8ull * 1024 * 2048];   //  32 MB  Y^T
__device__ __half g_keysh   [8ull * 2048 * 1024];   //  32 MB  proj -> LN'd keys
__device__ __half g_queriesh[8ull * 2048 * 1024];   //  32 MB  proj -> LN'd queries
__device__ __half g_alphah  [8ull * 2048 * 2048];   //  64 MB  exp(logits)
__device__ float  g_rowsum  [8ull * 2048];          //  64 KB  softmax denominators

// ---------------- helpers ------------------------------------------------------
__device__ __forceinline__ uint32_t smem_u32(const void* p) {
    uint32_t a;
    asm("{ .reg .u64 t; cvta.to.shared.u64 t, %1; cvt.u32.u64 %0, t; }"
        : "=r"(a) : "l"(p));
    return a;
}

__device__ __forceinline__ void mma_fp16(float* c, const uint32_t* a, const uint32_t* b) {
    asm volatile(
        "mma.sync.aligned.m16n8k16.row.col.f32.f16.f16.f32 "
        "{%0,%1,%2,%3}, {%4,%5,%6,%7}, {%8,%9}, {%0,%1,%2,%3};\n"
        : "+f"(c[0]), "+f"(c[1]), "+f"(c[2]), "+f"(c[3])
        : "r"(a[0]), "r"(a[1]), "r"(a[2]), "r"(a[3]), "r"(b[0]), "r"(b[1]));
}

__device__ __forceinline__ void ldsm4(uint32_t* r, uint32_t addr) {
    asm volatile("ldmatrix.sync.aligned.m8n8.x4.shared.b16 {%0,%1,%2,%3}, [%4];"
                 : "=r"(r[0]), "=r"(r[1]), "=r"(r[2]), "=r"(r[3]) : "r"(addr));
}

__device__ __forceinline__ void cp16(uint32_t dst, const void* src) {
    asm volatile("cp.async.cg.shared.global [%0], [%1], 16;"
                 :: "r"(dst), "l"(src) : "memory");
}
#define CP_COMMIT() asm volatile("cp.async.commit_group;" ::: "memory")

#define SWZ(o) ((o) ^ ((((uint32_t)(o)) >> 3) & 0x70u))

// ---------------- fp16 tensor GEMM (R10 mainloop, untouched) --------------------
// C = A[M,K] * B[N,K]^T.  CTA tile 128x128, BK=64, 3-stage cp.async with early
// burst prefetch, 256 threads, warp tile 32x64.
// EPI 0: C half (plain convert); blockIdx.z selects pair (A0,B0,C0)/(A1,B1,C1)
// EPI 1: C half = exp(acc/1024), + rowsum  [QK logits]   (z = batch)
// EPI 2: C f32  = acc / rowsum[row]        [PV output]   (z = batch)
#define TILEB  16384
#define STAGEB 32768
#define GSMEM  (3 * STAGEB)   // 96 KB -> 2 CTAs/SM

__device__ __forceinline__ void load_stage(
    const __half* A, const __half* B, int Kd, int row0, int col0, int kk,
    uint32_t abuf, uint32_t bbuf, int tid)
{
#pragma unroll
    for (int i = 0; i < 4; i++) {
        int ch = tid + i * 256;
        int r = ch >> 3, c = ch & 7;
        cp16(abuf + SWZ(r * 128 + c * 16),
             A + (long long)(row0 + r) * Kd + kk + c * 8);
    }
#pragma unroll
    for (int i = 0; i < 4; i++) {
        int ch = tid + i * 256;
        int r = ch >> 3, c = ch & 7;
        cp16(bbuf + SWZ(r * 128 + c * 16),
             B + (long long)(col0 + r) * Kd + kk + c * 8);
    }
    CP_COMMIT();
}

template <int EPI>
__global__ __launch_bounds__(256, 2)
void gemm_h(const __half* __restrict__ A, const __half* __restrict__ B,
            void* __restrict__ Cv,
            const __half* __restrict__ A1, const __half* __restrict__ B1,
            void* __restrict__ C1,
            float* __restrict__ rowsum,
            int M, int N, int Kd,
            long long sA, long long sB, long long sC, long long sR)
{
    extern __shared__ __align__(1024) char smem[];
    if (EPI == 0) {
        if (blockIdx.z) { A = A1; B = B1; Cv = C1; }
    } else {
        A += (long long)blockIdx.z * sA;
        B += (long long)blockIdx.z * sB;
        rowsum += (long long)blockIdx.z * sR;
    }

    const uint32_t sbase = smem_u32(smem);
    const int tid  = threadIdx.x;
    const int warp = tid >> 5;
    const int lane = tid & 31;
    const int gid  = lane >> 2;
    const int tig  = lane & 3;
    const int warp_m = warp & 3;
    const int warp_n = warp >> 2;
    const int row0 = blockIdx.y * 128;
    const int col0 = blockIdx.x * 128;

    const int l7 = lane & 7;
    uint32_t aoff[2], axm[2];
#pragma unroll
    for (int mt = 0; mt < 2; mt++) {
        int row = warp_m * 32 + mt * 16 + ((lane >> 3) & 1) * 8 + l7;
        aoff[mt] = (uint32_t)row * 128;
        axm[mt]  = (uint32_t)(row & 7) * 16;
    }
    const uint32_t aq = (uint32_t)((lane >> 4) & 1) * 16;
    uint32_t boff[4], bxm[4];
#pragma unroll
    for (int p = 0; p < 4; p++) {
        int row = warp_n * 64 + p * 16 + ((lane >> 4) & 1) * 8 + l7;
        boff[p] = (uint32_t)row * 128;
        bxm[p]  = (uint32_t)(row & 7) * 16;
    }
    const uint32_t bq = (uint32_t)((lane >> 3) & 1) * 16;

    float acc[2][8][4];
#pragma unroll
    for (int i = 0; i < 2; i++)
#pragma unroll
        for (int j = 0; j < 8; j++)
#pragma unroll
            for (int l = 0; l < 4; l++) acc[i][j][l] = 0.f;

    const int nst = Kd / 64;

    load_stage(A, B, Kd, row0, col0, 0,  sbase, sbase + TILEB, tid);
    load_stage(A, B, Kd, row0, col0, 64, sbase + STAGEB, sbase + STAGEB + TILEB, tid);

    for (int s = 0; s < nst; s++) {
        if (s + 1 < nst)
            asm volatile("cp.async.wait_group 1;" ::: "memory");
        else
            asm volatile("cp.async.wait_group 0;" ::: "memory");
        __syncthreads();

        // early prefetch of stage s+2 into buffer (s+2)%3 (free after barrier)
        if (s + 2 < nst) {
            int t = s + 2;
            const uint32_t nabuf = sbase + (t % 3) * STAGEB;
            load_stage(A, B, Kd, row0, col0, t * 64, nabuf, nabuf + TILEB, tid);
        }

        const uint32_t abuf = sbase + (s % 3) * STAGEB;
        const uint32_t bbuf = abuf + TILEB;

#pragma unroll
        for (int kg = 0; kg < 4; kg++) {
            uint32_t a[2][4], b[4][4];
#pragma unroll
            for (int mt = 0; mt < 2; mt++)
                ldsm4(a[mt], abuf + aoff[mt] + (((uint32_t)kg * 32 + aq) ^ axm[mt]));
#pragma unroll
            for (int p = 0; p < 4; p++)
                ldsm4(b[p], bbuf + boff[p] + (((uint32_t)kg * 32 + bq) ^ bxm[p]));
#pragma unroll
            for (int mt = 0; mt < 2; mt++)
#pragma unroll
                for (int nt = 0; nt < 8; nt++)
                    mma_fp16(acc[mt][nt], a[mt], &b[nt >> 1][(nt & 1) * 2]);
        }
    }

    // ---- epilogue ----
    if (EPI == 0) {
        __half* C = (__half*)Cv;
#pragma unroll
        for (int mt = 0; mt < 2; mt++) {
            int r = row0 + warp_m * 32 + mt * 16 + gid;
#pragma unroll
            for (int nt = 0; nt < 8; nt++) {
                int c = col0 + warp_n * 64 + nt * 8 + tig * 2;
                *(__half2*)(C + (long long)r * N + c) =
                    __floats2half2_rn(acc[mt][nt][0], acc[mt][nt][1]);
                *(__half2*)(C + (long long)(r + 8) * N + c) =
                    __floats2half2_rn(acc[mt][nt][2], acc[mt][nt][3]);
            }
        }
    } else if (EPI == 1) {
        __half* C = (__half*)Cv + (long long)blockIdx.z * sC;
        const float sc = 1.4426950408889634f / 1024.0f;  // log2(e)/H
#pragma unroll
        for (int mt = 0; mt < 2; mt++) {
            int r = row0 + warp_m * 32 + mt * 16 + gid;
            float rs0 = 0.f, rs1 = 0.f;
#pragma unroll
            for (int nt = 0; nt < 8; nt++) {
                int c = col0 + warp_n * 64 + nt * 8 + tig * 2;
                float p0 = exp2f(acc[mt][nt][0] * sc);
                float p1 = exp2f(acc[mt][nt][1] * sc);
                float p2 = exp2f(acc[mt][nt][2] * sc);
                float p3 = exp2f(acc[mt][nt][3] * sc);
                *(__half2*)(C + (long long)r * N + c)       = __floats2half2_rn(p0, p1);
                *(__half2*)(C + (long long)(r + 8) * N + c) = __floats2half2_rn(p2, p3);
                rs0 += p0 + p1;
                rs1 += p2 + p3;
            }
            rs0 += __shfl_xor_sync(0xffffffffu, rs0, 1);
            rs0 += __shfl_xor_sync(0xffffffffu, rs0, 2);
            rs1 += __shfl_xor_sync(0xffffffffu, rs1, 1);
            rs1 += __shfl_xor_sync(0xffffffffu, rs1, 2);
            if (tig == 0) {
                atomicAdd(&rowsum[r], rs0);
                atomicAdd(&rowsum[r + 8], rs1);
            }
        }
    } else {
        float* C = (float*)Cv + (long long)blockIdx.z * sC;
#pragma unroll
        for (int mt = 0; mt < 2; mt++) {
            int r = row0 + warp_m * 32 + mt * 16 + gid;
            const float i0 = 1.0f / rowsum[r];
            const float i1 = 1.0f / rowsum[r + 8];
#pragma unroll
            for (int nt = 0; nt < 8; nt++) {
                int c = col0 + warp_n * 64 + nt * 8 + tig * 2;
                *(float2*)(C + (long long)r * N + c) =
                    make_float2(acc[mt][nt][0] * i0, acc[mt][nt][1] * i0);
                *(float2*)(C + (long long)(r + 8) * N + c) =
                    make_float2(acc[mt][nt][2] * i1, acc[mt][nt][3] * i1);
            }
        }
    }
}

// ---------------- merged pre-pass ------------------------------------------------
// z in [0,B):   Y batch z  -> yh (convert) + yth (convert+transpose)
// z in [B,2B):  X batch z-B -> xh (convert only)
__global__ __launch_bounds__(256) void prep_xy(
    const float* __restrict__ Yin, __half* __restrict__ yh, __half* __restrict__ yt,
    const float* __restrict__ Xin, __half* __restrict__ xh,
    int R, int C, long long sIn, long long sOut, int B)
{
    const int z = blockIdx.z;
    const int r0 = blockIdx.y * 32, c0 = blockIdx.x * 32;
    const int tx = threadIdx.x & 31, ty = threadIdx.x >> 5;

    if (z < B) {
        const float* in = Yin + (long long)z * sIn;
        __half* oh = yh + (long long)z * sIn;
        __half* ot = yt + (long long)z * sOut;
        __shared__ float t[32][33];
#pragma unroll
        for (int i = 0; i < 32; i += 8) {
            float v = in[(long long)(r0 + ty + i) * C + c0 + tx];
            t[ty + i][tx] = v;
            oh[(long long)(r0 + ty + i) * C + c0 + tx] = __float2half_rn(v);
        }
        __syncthreads();
#pragma unroll
        for (int i = 0; i < 32; i += 8)
            ot[(long long)(c0 + ty + i) * R + r0 + tx] = __float2half_rn(t[tx][ty + i]);
    } else {
        const float* in = Xin + (long long)(z - B) * sIn;
        __half* oh = xh + (long long)(z - B) * sIn;
#pragma unroll
        for (int i = 0; i < 32; i += 8) {
            float v = in[(long long)(r0 + ty + i) * C + c0 + tx];
            oh[(long long)(r0 + ty + i) * C + c0 + tx] = __float2half_rn(v);
        }
    }
}

// Transpose BOTH K and Q in one launch (blockIdx.z selects).
__global__ __launch_bounds__(256) void trans2_half(
    const float* __restrict__ in0, __half* __restrict__ out0,
    const float* __restrict__ in1, __half* __restrict__ out1,
    int R, int C)
{
    const float* in = blockIdx.z ? in1 : in0;
    __half* out = blockIdx.z ? out1 : out0;
    __shared__ float t[32][33];
    const int r0 = blockIdx.y * 32, c0 = blockIdx.x * 32;
    const int tx = threadIdx.x & 31, ty = threadIdx.x >> 5;
#pragma unroll
    for (int i = 0; i < 32; i += 8)
        t[ty + i][tx] = in[(long long)(r0 + ty + i) * C + c0 + tx];
    __syncthreads();
#pragma unroll
    for (int i = 0; i < 32; i += 8)
        out[(long long)(c0 + ty + i) * R + r0 + tx] = __float2half_rn(t[tx][ty + i]);
}

// ---------------- fused layernorm (vectorized) + rowsum zeroing -----------------
__global__ __launch_bounds__(128) void layernorm2_kernel(
    __half* __restrict__ d0, const float* __restrict__ ga0, const float* __restrict__ be0,
    __half* __restrict__ d1, const float* __restrict__ ga1, const float* __restrict__ be1,
    float* __restrict__ rowsum)
{
    const int H = 1024;
    __half* row = (blockIdx.y ? d1 : d0) + (long long)blockIdx.x * H;
    const float* gamma = blockIdx.y ? ga1 : ga0;
    const float* beta  = blockIdx.y ? be1 : be0;
    const int t = threadIdx.x;
    const int lane = t & 31, wid = t >> 5;

    if (blockIdx.y == 0 && t == 0) rowsum[blockIdx.x] = 0.f;

    uint4 v = *(uint4*)(row + t * 8);
    __half2 h[4];
    h[0] = *(__half2*)&v.x; h[1] = *(__half2*)&v.y;
    h[2] = *(__half2*)&v.z; h[3] = *(__half2*)&v.w;

    float f[8];
#pragma unroll
    for (int i = 0; i < 4; i++) {
        float2 p = __half22float2(h[i]);
        f[i * 2] = p.x; f[i * 2 + 1] = p.y;
    }
    float s = 0.f, q = 0.f;
#pragma unroll
    for (int i = 0; i < 8; i++) { s += f[i]; q += f[i] * f[i]; }

#pragma unroll
    for (int o = 16; o > 0; o >>= 1) {
        s += __shfl_xor_sync(0xffffffffu, s, o);
        q += __shfl_xor_sync(0xffffffffu, q, o);
    }
    __shared__ float ss[4], sq[4];
    if (lane == 0) { ss[wid] = s; sq[wid] = q; }
    __syncthreads();
    s = ss[0] + ss[1] + ss[2] + ss[3];
    q = sq[0] + sq[1] + sq[2] + sq[3];

    const float mu  = s * (1.f / 1024.f);
    const float var = q * (1.f / 1024.f) - mu * mu;
    const float inv = rsqrtf(var + 1e-5f);

    const int c0 = t * 8;
    float4 g0 = *(const float4*)(gamma + c0);
    float4 g1v = *(const float4*)(gamma + c0 + 4);
    float4 b0 = *(const float4*)(beta + c0);
    float4 b1v = *(const float4*)(beta + c0 + 4);
    const float gg[8] = {g0.x, g0.y, g0.z, g0.w, g1v.x, g1v.y, g1v.z, g1v.w};
    const float bb[8] = {b0.x, b0.y, b0.z, b0.w, b1v.x, b1v.y, b1v.z, b1v.w};

    uint4 o;
    __half2* oh = (__half2*)&o;
#pragma unroll
    for (int i = 0; i < 4; i++) {
        float r0 = (f[i * 2]     - mu) * inv * gg[i * 2]     + bb[i * 2];
        float r1 = (f[i * 2 + 1] - mu) * inv * gg[i * 2 + 1] + bb[i * 2 + 1];
        oh[i] = __floats2half2_rn(r0, r1);
    }
    *(uint4*)(row + t * 8) = o;
}

// ---------------- kernel_launch --------------------------------------------------
extern "C" void kernel_launch(void* const* d_in, const int* in_sizes, int n_in,
                              void* d_out, int out_size)
{
    const float* X  = (const float*)d_in[0];
    const float* Y  = (const float*)d_in[1];
    const float* K  = (const float*)d_in[2];
    const float* Q  = (const float*)d_in[3];
    const float* g1 = (const float*)d_in[4];
    const float* b1 = (const float*)d_in[5];
    const float* g2 = (const float*)d_in[6];
    const float* b2 = (const float*)d_in[7];
    float* out = (float*)d_out;

    __half *xh, *yh, *kth, *qth, *yth, *keysh, *queriesh, *alphah;
    float* rowsum;
    cudaGetSymbolAddress((void**)&xh,       g_xh);
    cudaGetSymbolAddress((void**)&yh,       g_yh);
    cudaGetSymbolAddress((void**)&kth,      g_kth);
    cudaGetSymbolAddress((void**)&qth,      g_qth);
    cudaGetSymbolAddress((void**)&yth,      g_yth);
    cudaGetSymbolAddress((void**)&keysh,    g_keysh);
    cudaGetSymbolAddress((void**)&queriesh, g_queriesh);
    cudaGetSymbolAddress((void**)&alphah,   g_alphah);
    cudaGetSymbolAddress((void**)&rowsum,   g_rowsum);

    cudaFuncSetAttribute(gemm_h<0>, cudaFuncAttributeMaxDynamicSharedMemorySize, GSMEM);
    cudaFuncSetAttribute(gemm_h<1>, cudaFuncAttributeMaxDynamicSharedMemorySize, GSMEM);
    cudaFuncSetAttribute(gemm_h<2>, cudaFuncAttributeMaxDynamicSharedMemorySize, GSMEM);

    const int B = 8, S = 2048, F = 1024, H = 1024;
    const long long sQK = (long long)S * H;
    const long long sAL = (long long)S * S;
    const long long sY  = (long long)S * F;
    const long long sYT = (long long)F * S;

    // 1) merged pre-pass: Y -> yh+yth, X -> xh (one launch) ; K,Q transposes
    prep_xy<<<dim3(F / 32, S / 32, 2 * B), 256>>>(Y, yh, yth, X, xh, S, F, sY, sYT, B);
    trans2_half<<<dim3(H / 32, F / 32, 2), 256>>>(K, kth, Q, qth, F, H);

    // 2) both projections in ONE launch (z selects pair)
    gemm_h<0><<<dim3(H / 128, (B * S) / 128, 2), 256, GSMEM>>>(
        yh, kth, keysh, xh, qth, queriesh, nullptr,
        B * S, H, F, 0, 0, 0, 0);

    // 3) both layernorms (vectorized) + rowsum zeroing in one launch
    layernorm2_kernel<<<dim3(B * S, 2), 128>>>(keysh, g1, b1, queriesh, g2, b2, rowsum);

    // 4) QK logits + fused exp + row sums: alphah = exp(q.k/H)
    gemm_h<1><<<dim3(S / 128, S / 128, B), 256, GSMEM>>>(
        queriesh, keysh, alphah, nullptr, nullptr, nullptr, rowsum,
        S, S, H, sQK, sQK, sAL, S);

    // 5) PV + fused division: out = (alphah @ yth^T) / rowsum
    gemm_h<2><<<dim3(F / 128, S / 128, B), 256, GSMEM>>>(
        alphah, yth, out, nullptr, nullptr, nullptr, rowsum,
        S, F, S, sAL, sYT, sY, S);
}

// round 13
// speedup vs baseline: 1.0625x; 1.0072x over previous
#include <cuda_runtime.h>
#include <cuda_fp16.h>
#include <cstdint>

// ----------------------------------------------------------------------------
// Attention_53944789237811  (round 13: LN stats fused into projection epilogue)
//   keys    = LayerNorm(Y @ K) * g1 + b1          [B,S,H]
//   queries = LayerNorm(X @ Q) * g2 + b2          [B,S,H]
//   alpha   = softmax(queries @ keys^T / H)       [B,S,S]
//   out     = alpha @ Y                           [B,S,F]
// B=8, S=2048, F=H=1024.
// GEMM mainloop = R10 (proven local optimum). Projection epilogue accumulates
// per-row sum/sumsq (f32, pre-rounding) via quad-reduced atomics; the LN pass
// is then barrier-free (load stats, normalize, store).
// ----------------------------------------------------------------------------

#define NROWS 16384   // B*S

// ---------------- scratch (device globals; no cudaMalloc allowed) ------------
__device__ __half g_xh      [8ull * 2048 * 1024];   //  32 MB  X (half)
__device__ __half g_yh      [8ull * 2048 * 1024];   //  32 MB  Y (half)
__device__ __half g_kth     [1024ull * 1024];       //   2 MB  K^T
__device__ __half g_qth     [1024ull * 1024];       //   2 MB  Q^T
__device__ __half g_yth     [8ull * 1024 * 2048];   //  32 MB  Y^T
__device__ __half g_keysh   [8ull * 2048 * 1024];   //  32 MB  proj -> LN'd keys
__device__ __half g_queriesh[8ull * 2048 * 1024];   //  32 MB  proj -> LN'd queries
__device__ __half g_alphah  [8ull * 2048 * 2048];   //  64 MB  exp(logits)
__device__ float  g_rowsum  [NROWS];                //  64 KB  softmax denominators
__device__ float  g_stats   [4ull * NROWS];         // 256 KB  [tensor][sum|sumsq][row]

// ---------------- helpers ------------------------------------------------------
__device__ __forceinline__ uint32_t smem_u32(const void* p) {
    uint32_t a;
    asm("{ .reg .u64 t; cvta.to.shared.u64 t, %1; cvt.u32.u64 %0, t; }"
        : "=r"(a) : "l"(p));
    return a;
}

__device__ __forceinline__ void mma_fp16(float* c, const uint32_t* a, const uint32_t* b) {
    asm volatile(
        "mma.sync.aligned.m16n8k16.row.col.f32.f16.f16.f32 "
        "{%0,%1,%2,%3}, {%4,%5,%6,%7}, {%8,%9}, {%0,%1,%2,%3};\n"
        : "+f"(c[0]), "+f"(c[1]), "+f"(c[2]), "+f"(c[3])
        : "r"(a[0]), "r"(a[1]), "r"(a[2]), "r"(a[3]), "r"(b[0]), "r"(b[1]));
}

__device__ __forceinline__ void ldsm4(uint32_t* r, uint32_t addr) {
    asm volatile("ldmatrix.sync.aligned.m8n8.x4.shared.b16 {%0,%1,%2,%3}, [%4];"
                 : "=r"(r[0]), "=r"(r[1]), "=r"(r[2]), "=r"(r[3]) : "r"(addr));
}

__device__ __forceinline__ void cp16(uint32_t dst, const void* src) {
    asm volatile("cp.async.cg.shared.global [%0], [%1], 16;"
                 :: "r"(dst), "l"(src) : "memory");
}
#define CP_COMMIT() asm volatile("cp.async.commit_group;" ::: "memory")

#define SWZ(o) ((o) ^ ((((uint32_t)(o)) >> 3) & 0x70u))

// ---------------- fp16 tensor GEMM (R10 mainloop, untouched) --------------------
// C = A[M,K] * B[N,K]^T.  CTA tile 128x128, BK=64, 3-stage cp.async with early
// burst prefetch, 256 threads, warp tile 32x64.
// EPI 0: C half + row sum/sumsq atomics; z selects (A0,B0,C0,stats0)/(A1,...)
// EPI 1: C half = exp(acc/1024), + rowsum  [QK logits]   (z = batch)
// EPI 2: C f32  = acc / rowsum[row]        [PV output]   (z = batch)
#define TILEB  16384
#define STAGEB 32768
#define GSMEM  (3 * STAGEB)   // 96 KB -> 2 CTAs/SM

__device__ __forceinline__ void load_stage(
    const __half* A, const __half* B, int Kd, int row0, int col0, int kk,
    uint32_t abuf, uint32_t bbuf, int tid)
{
#pragma unroll
    for (int i = 0; i < 4; i++) {
        int ch = tid + i * 256;
        int r = ch >> 3, c = ch & 7;
        cp16(abuf + SWZ(r * 128 + c * 16),
             A + (long long)(row0 + r) * Kd + kk + c * 8);
    }
#pragma unroll
    for (int i = 0; i < 4; i++) {
        int ch = tid + i * 256;
        int r = ch >> 3, c = ch & 7;
        cp16(bbuf + SWZ(r * 128 + c * 16),
             B + (long long)(col0 + r) * Kd + kk + c * 8);
    }
    CP_COMMIT();
}

template <int EPI>
__global__ __launch_bounds__(256, 2)
void gemm_h(const __half* __restrict__ A, const __half* __restrict__ B,
            void* __restrict__ Cv,
            const __half* __restrict__ A1, const __half* __restrict__ B1,
            void* __restrict__ C1,
            float* __restrict__ rowsum, float* __restrict__ stats,
            int M, int N, int Kd,
            long long sA, long long sB, long long sC, long long sR)
{
    extern __shared__ __align__(1024) char smem[];
    if (EPI == 0) {
        if (blockIdx.z) { A = A1; B = B1; Cv = C1; stats += 2 * NROWS; }
    } else {
        A += (long long)blockIdx.z * sA;
        B += (long long)blockIdx.z * sB;
        rowsum += (long long)blockIdx.z * sR;
    }

    const uint32_t sbase = smem_u32(smem);
    const int tid  = threadIdx.x;
    const int warp = tid >> 5;
    const int lane = tid & 31;
    const int gid  = lane >> 2;
    const int tig  = lane & 3;
    const int warp_m = warp & 3;
    const int warp_n = warp >> 2;
    const int row0 = blockIdx.y * 128;
    const int col0 = blockIdx.x * 128;

    const int l7 = lane & 7;
    uint32_t aoff[2], axm[2];
#pragma unroll
    for (int mt = 0; mt < 2; mt++) {
        int row = warp_m * 32 + mt * 16 + ((lane >> 3) & 1) * 8 + l7;
        aoff[mt] = (uint32_t)row * 128;
        axm[mt]  = (uint32_t)(row & 7) * 16;
    }
    const uint32_t aq = (uint32_t)((lane >> 4) & 1) * 16;
    uint32_t boff[4], bxm[4];
#pragma unroll
    for (int p = 0; p < 4; p++) {
        int row = warp_n * 64 + p * 16 + ((lane >> 4) & 1) * 8 + l7;
        boff[p] = (uint32_t)row * 128;
        bxm[p]  = (uint32_t)(row & 7) * 16;
    }
    const uint32_t bq = (uint32_t)((lane >> 3) & 1) * 16;

    float acc[2][8][4];
#pragma unroll
    for (int i = 0; i < 2; i++)
#pragma unroll
        for (int j = 0; j < 8; j++)
#pragma unroll
            for (int l = 0; l < 4; l++) acc[i][j][l] = 0.f;

    const int nst = Kd / 64;

    load_stage(A, B, Kd, row0, col0, 0,  sbase, sbase + TILEB, tid);
    load_stage(A, B, Kd, row0, col0, 64, sbase + STAGEB, sbase + STAGEB + TILEB, tid);

    for (int s = 0; s < nst; s++) {
        if (s + 1 < nst)
            asm volatile("cp.async.wait_group 1;" ::: "memory");
        else
            asm volatile("cp.async.wait_group 0;" ::: "memory");
        __syncthreads();

        // early prefetch of stage s+2 into buffer (s+2)%3 (free after barrier)
        if (s + 2 < nst) {
            int t = s + 2;
            const uint32_t nabuf = sbase + (t % 3) * STAGEB;
            load_stage(A, B, Kd, row0, col0, t * 64, nabuf, nabuf + TILEB, tid);
        }

        const uint32_t abuf = sbase + (s % 3) * STAGEB;
        const uint32_t bbuf = abuf + TILEB;

#pragma unroll
        for (int kg = 0; kg < 4; kg++) {
            uint32_t a[2][4], b[4][4];
#pragma unroll
            for (int mt = 0; mt < 2; mt++)
                ldsm4(a[mt], abuf + aoff[mt] + (((uint32_t)kg * 32 + aq) ^ axm[mt]));
#pragma unroll
            for (int p = 0; p < 4; p++)
                ldsm4(b[p], bbuf + boff[p] + (((uint32_t)kg * 32 + bq) ^ bxm[p]));
#pragma unroll
            for (int mt = 0; mt < 2; mt++)
#pragma unroll
                for (int nt = 0; nt < 8; nt++)
                    mma_fp16(acc[mt][nt], a[mt], &b[nt >> 1][(nt & 1) * 2]);
        }
    }

    // ---- epilogue ----
    if (EPI == 0) {
        __half* C = (__half*)Cv;
        float* ssum = stats;
        float* ssq  = stats + NROWS;
#pragma unroll
        for (int mt = 0; mt < 2; mt++) {
            int r = row0 + warp_m * 32 + mt * 16 + gid;
            float s0 = 0.f, q0 = 0.f, s1 = 0.f, q1 = 0.f;
#pragma unroll
            for (int nt = 0; nt < 8; nt++) {
                int c = col0 + warp_n * 64 + nt * 8 + tig * 2;
                float a0 = acc[mt][nt][0], a1 = acc[mt][nt][1];
                float a2 = acc[mt][nt][2], a3 = acc[mt][nt][3];
                *(__half2*)(C + (long long)r * N + c)       = __floats2half2_rn(a0, a1);
                *(__half2*)(C + (long long)(r + 8) * N + c) = __floats2half2_rn(a2, a3);
                s0 += a0 + a1;  q0 += a0 * a0 + a1 * a1;
                s1 += a2 + a3;  q1 += a2 * a2 + a3 * a3;
            }
            s0 += __shfl_xor_sync(0xffffffffu, s0, 1);
            s0 += __shfl_xor_sync(0xffffffffu, s0, 2);
            q0 += __shfl_xor_sync(0xffffffffu, q0, 1);
            q0 += __shfl_xor_sync(0xffffffffu, q0, 2);
            s1 += __shfl_xor_sync(0xffffffffu, s1, 1);
            s1 += __shfl_xor_sync(0xffffffffu, s1, 2);
            q1 += __shfl_xor_sync(0xffffffffu, q1, 1);
            q1 += __shfl_xor_sync(0xffffffffu, q1, 2);
            if (tig == 0) {
                atomicAdd(&ssum[r], s0);  atomicAdd(&ssq[r], q0);
                atomicAdd(&ssum[r + 8], s1);  atomicAdd(&ssq[r + 8], q1);
            }
        }
    } else if (EPI == 1) {
        __half* C = (__half*)Cv + (long long)blockIdx.z * sC;
        const float sc = 1.4426950408889634f / 1024.0f;  // log2(e)/H
#pragma unroll
        for (int mt = 0; mt < 2; mt++) {
            int r = row0 + warp_m * 32 + mt * 16 + gid;
            float rs0 = 0.f, rs1 = 0.f;
#pragma unroll
            for (int nt = 0; nt < 8; nt++) {
                int c = col0 + warp_n * 64 + nt * 8 + tig * 2;
                float p0 = exp2f(acc[mt][nt][0] * sc);
                float p1 = exp2f(acc[mt][nt][1] * sc);
                float p2 = exp2f(acc[mt][nt][2] * sc);
                float p3 = exp2f(acc[mt][nt][3] * sc);
                *(__half2*)(C + (long long)r * N + c)       = __floats2half2_rn(p0, p1);
                *(__half2*)(C + (long long)(r + 8) * N + c) = __floats2half2_rn(p2, p3);
                rs0 += p0 + p1;
                rs1 += p2 + p3;
            }
            rs0 += __shfl_xor_sync(0xffffffffu, rs0, 1);
            rs0 += __shfl_xor_sync(0xffffffffu, rs0, 2);
            rs1 += __shfl_xor_sync(0xffffffffu, rs1, 1);
            rs1 += __shfl_xor_sync(0xffffffffu, rs1, 2);
            if (tig == 0) {
                atomicAdd(&rowsum[r], rs0);
                atomicAdd(&rowsum[r + 8], rs1);
            }
        }
    } else {
        float* C = (float*)Cv + (long long)blockIdx.z * sC;
#pragma unroll
        for (int mt = 0; mt < 2; mt++) {
            int r = row0 + warp_m * 32 + mt * 16 + gid;
            const float i0 = 1.0f / rowsum[r];
            const float i1 = 1.0f / rowsum[r + 8];
#pragma unroll
            for (int nt = 0; nt < 8; nt++) {
                int c = col0 + warp_n * 64 + nt * 8 + tig * 2;
                *(float2*)(C + (long long)r * N + c) =
                    make_float2(acc[mt][nt][0] * i0, acc[mt][nt][1] * i0);
                *(float2*)(C + (long long)(r + 8) * N + c) =
                    make_float2(acc[mt][nt][2] * i1, acc[mt][nt][3] * i1);
            }
        }
    }
}

// ---------------- pre/aux kernels (R10 forms) ------------------------------------
__global__ __launch_bounds__(256) void cvt_half(const float4* __restrict__ in,
                                                __half2* __restrict__ out, int n4)
{
    int i = blockIdx.x * 256 + threadIdx.x;
    int stride = gridDim.x * 256;
    for (; i < n4; i += stride) {
        float4 v = in[i];
        out[i * 2 + 0] = __floats2half2_rn(v.x, v.y);
        out[i * 2 + 1] = __floats2half2_rn(v.z, v.w);
    }
}

// Read Y once; emit yh (straight half copy) and yth (transposed half).
__global__ __launch_bounds__(256) void cvt_trans_half(
    const float* __restrict__ in, __half* __restrict__ oh, __half* __restrict__ ot,
    int R, int C, long long sIn, long long sOut)
{
    in += (long long)blockIdx.z * sIn;
    oh += (long long)blockIdx.z * sIn;
    ot += (long long)blockIdx.z * sOut;
    __shared__ float t[32][33];
    const int r0 = blockIdx.y * 32, c0 = blockIdx.x * 32;
    const int tx = threadIdx.x & 31, ty = threadIdx.x >> 5;
#pragma unroll
    for (int i = 0; i < 32; i += 8) {
        float v = in[(long long)(r0 + ty + i) * C + c0 + tx];
        t[ty + i][tx] = v;
        oh[(long long)(r0 + ty + i) * C + c0 + tx] = __float2half_rn(v);
    }
    __syncthreads();
#pragma unroll
    for (int i = 0; i < 32; i += 8)
        ot[(long long)(c0 + ty + i) * R + r0 + tx] = __float2half_rn(t[tx][ty + i]);
}

// Transpose BOTH K and Q in one launch (blockIdx.z selects).
__global__ __launch_bounds__(256) void trans2_half(
    const float* __restrict__ in0, __half* __restrict__ out0,
    const float* __restrict__ in1, __half* __restrict__ out1,
    int R, int C)
{
    const float* in = blockIdx.z ? in1 : in0;
    __half* out = blockIdx.z ? out1 : out0;
    __shared__ float t[32][33];
    const int r0 = blockIdx.y * 32, c0 = blockIdx.x * 32;
    const int tx = threadIdx.x & 31, ty = threadIdx.x >> 5;
#pragma unroll
    for (int i = 0; i < 32; i += 8)
        t[ty + i][tx] = in[(long long)(r0 + ty + i) * C + c0 + tx];
    __syncthreads();
#pragma unroll
    for (int i = 0; i < 32; i += 8)
        out[(long long)(c0 + ty + i) * R + r0 + tx] = __float2half_rn(t[tx][ty + i]);
}

// Clear stats (4*NROWS) + rowsum (NROWS)
__global__ __launch_bounds__(256) void clear_aux(float* __restrict__ stats,
                                                 float* __restrict__ rowsum)
{
    int i = blockIdx.x * 256 + threadIdx.x;
    if (i < 4 * NROWS) stats[i] = 0.f;
    else if (i < 5 * NROWS) rowsum[i - 4 * NROWS] = 0.f;
}

// ---------------- barrier-free layernorm (stats precomputed) --------------------
// 128 threads/row, one uint4 (8 halves) per thread. blockIdx.y selects tensor.
__global__ __launch_bounds__(128) void layernorm2_kernel(
    __half* __restrict__ d0, const float* __restrict__ ga0, const float* __restrict__ be0,
    __half* __restrict__ d1, const float* __restrict__ ga1, const float* __restrict__ be1,
    const float* __restrict__ stats)
{
    const int H = 1024;
    __half* row = (blockIdx.y ? d1 : d0) + (long long)blockIdx.x * H;
    const float* gamma = blockIdx.y ? ga1 : ga0;
    const float* beta  = blockIdx.y ? be1 : be0;
    const float* st = stats + (blockIdx.y ? 2 * NROWS : 0);
    const int t = threadIdx.x;

    const float s = st[blockIdx.x];
    const float q = st[NROWS + blockIdx.x];
    const float mu  = s * (1.f / 1024.f);
    const float var = q * (1.f / 1024.f) - mu * mu;
    const float inv = rsqrtf(var + 1e-5f);

    uint4 v = *(uint4*)(row + t * 8);
    __half2 h[4];
    h[0] = *(__half2*)&v.x; h[1] = *(__half2*)&v.y;
    h[2] = *(__half2*)&v.z; h[3] = *(__half2*)&v.w;

    float f[8];
#pragma unroll
    for (int i = 0; i < 4; i++) {
        float2 p = __half22float2(h[i]);
        f[i * 2] = p.x; f[i * 2 + 1] = p.y;
    }

    const int c0 = t * 8;
    float4 g0 = *(const float4*)(gamma + c0);
    float4 g1v = *(const float4*)(gamma + c0 + 4);
    float4 b0 = *(const float4*)(beta + c0);
    float4 b1v = *(const float4*)(beta + c0 + 4);
    const float gg[8] = {g0.x, g0.y, g0.z, g0.w, g1v.x, g1v.y, g1v.z, g1v.w};
    const float bb[8] = {b0.x, b0.y, b0.z, b0.w, b1v.x, b1v.y, b1v.z, b1v.w};

    uint4 o;
    __half2* oh = (__half2*)&o;
#pragma unroll
    for (int i = 0; i < 4; i++) {
        float r0 = (f[i * 2]     - mu) * inv * gg[i * 2]     + bb[i * 2];
        float r1 = (f[i * 2 + 1] - mu) * inv * gg[i * 2 + 1] + bb[i * 2 + 1];
        oh[i] = __floats2half2_rn(r0, r1);
    }
    *(uint4*)(row + t * 8) = o;
}

// ---------------- kernel_launch --------------------------------------------------
extern "C" void kernel_launch(void* const* d_in, const int* in_sizes, int n_in,
                              void* d_out, int out_size)
{
    const float* X  = (const float*)d_in[0];
    const float* Y  = (const float*)d_in[1];
    const float* K  = (const float*)d_in[2];
    const float* Q  = (const float*)d_in[3];
    const float* g1 = (const float*)d_in[4];
    const float* b1 = (const float*)d_in[5];
    const float* g2 = (const float*)d_in[6];
    const float* b2 = (const float*)d_in[7];
    float* out = (float*)d_out;

    __half *xh, *yh, *kth, *qth, *yth, *keysh, *queriesh, *alphah;
    float *rowsum, *stats;
    cudaGetSymbolAddress((void**)&xh,       g_xh);
    cudaGetSymbolAddress((void**)&yh,       g_yh);
    cudaGetSymbolAddress((void**)&kth,      g_kth);
    cudaGetSymbolAddress((void**)&qth,      g_qth);
    cudaGetSymbolAddress((void**)&yth,      g_yth);
    cudaGetSymbolAddress((void**)&keysh,    g_keysh);
    cudaGetSymbolAddress((void**)&queriesh, g_queriesh);
    cudaGetSymbolAddress((void**)&alphah,   g_alphah);
    cudaGetSymbolAddress((void**)&rowsum,   g_rowsum);
    cudaGetSymbolAddress((void**)&stats,    g_stats);

    cudaFuncSetAttribute(gemm_h<0>, cudaFuncAttributeMaxDynamicSharedMemorySize, GSMEM);
    cudaFuncSetAttribute(gemm_h<1>, cudaFuncAttributeMaxDynamicSharedMemorySize, GSMEM);
    cudaFuncSetAttribute(gemm_h<2>, cudaFuncAttributeMaxDynamicSharedMemorySize, GSMEM);

    const int B = 8, S = 2048, F = 1024, H = 1024;
    const long long nXY = (long long)B * S * F;
    const long long sQK = (long long)S * H;
    const long long sAL = (long long)S * S;
    const long long sY  = (long long)S * F;
    const long long sYT = (long long)F * S;

    // 1) clear stats+rowsum; fp16 conversions + transposes (R10 forms)
    clear_aux<<<(5 * NROWS + 255) / 256, 256>>>(stats, rowsum);
    cvt_half<<<2048, 256>>>((const float4*)X, (__half2*)xh, (int)(nXY / 4));
    cvt_trans_half<<<dim3(F / 32, S / 32, B), 256>>>(Y, yh, yth, S, F, sY, sYT);
    trans2_half<<<dim3(H / 32, F / 32, 2), 256>>>(K, kth, Q, qth, F, H);

    // 2) both projections in ONE launch (z selects pair); epilogue emits LN stats
    gemm_h<0><<<dim3(H / 128, (B * S) / 128, 2), 256, GSMEM>>>(
        yh, kth, keysh, xh, qth, queriesh, nullptr, stats,
        B * S, H, F, 0, 0, 0, 0);

    // 3) barrier-free layernorms (stats precomputed)
    layernorm2_kernel<<<dim3(B * S, 2), 128>>>(keysh, g1, b1, queriesh, g2, b2, stats);

    // 4) QK logits + fused exp + row sums: alphah = exp(q.k/H)
    gemm_h<1><<<dim3(S / 128, S / 128, B), 256, GSMEM>>>(
        queriesh, keysh, alphah, nullptr, nullptr, nullptr, rowsum, nullptr,
        S, S, H, sQK, sQK, sAL, S);

    // 5) PV + fused division: out = (alphah @ yth^T) / rowsum
    gemm_h<2><<<dim3(F / 128, S / 128, B), 256, GSMEM>>>(
        alphah, yth, out, nullptr, nullptr, nullptr, rowsum, nullptr,
        S, F, S, sAL, sYT, sY, S);
}

// round 14
// speedup vs baseline: 1.0625x; 1.0001x over previous
#include <cuda_runtime.h>
#include <cuda_fp16.h>
#include <cstdint>

// ----------------------------------------------------------------------------
// Attention_53944789237811  (round 14: R13 + LN row-batching + folded clear)
//   keys    = LayerNorm(Y @ K) * g1 + b1          [B,S,H]
//   queries = LayerNorm(X @ Q) * g2 + b2          [B,S,H]
//   alpha   = softmax(queries @ keys^T / H)       [B,S,S]
//   out     = alpha @ Y                           [B,S,F]
// B=8, S=2048, F=H=1024.
// ----------------------------------------------------------------------------

#define NROWS 16384   // B*S

// ---------------- scratch (device globals; no cudaMalloc allowed) ------------
__device__ __half g_xh      [8ull * 2048 * 1024];   //  32 MB  X (half)
__device__ __half g_yh      [8ull * 2048 * 1024];   //  32 MB  Y (half)
__device__ __half g_kth     [1024ull * 1024];       //   2 MB  K^T
__device__ __half g_qth     [1024ull * 1024];       //   2 MB  Q^T
__device__ __half g_yth     [8ull * 1024 * 2048];   //  32 MB  Y^T
__device__ __half g_keysh   [8ull * 2048 * 1024];   //  32 MB  proj -> LN'd keys
__device__ __half g_queriesh[8ull * 2048 * 1024];   //  32 MB  proj -> LN'd queries
__device__ __half g_alphah  [8ull * 2048 * 2048];   //  64 MB  exp(logits)
__device__ float  g_rowsum  [NROWS];                //  64 KB  softmax denominators
__device__ float  g_stats   [4ull * NROWS];         // 256 KB  [tensor][sum|sumsq][row]

// ---------------- helpers ------------------------------------------------------
__device__ __forceinline__ uint32_t smem_u32(const void* p) {
    uint32_t a;
    asm("{ .reg .u64 t; cvta.to.shared.u64 t, %1; cvt.u32.u64 %0, t; }"
        : "=r"(a) : "l"(p));
    return a;
}

__device__ __forceinline__ void mma_fp16(float* c, const uint32_t* a, const uint32_t* b) {
    asm volatile(
        "mma.sync.aligned.m16n8k16.row.col.f32.f16.f16.f32 "
        "{%0,%1,%2,%3}, {%4,%5,%6,%7}, {%8,%9}, {%0,%1,%2,%3};\n"
        : "+f"(c[0]), "+f"(c[1]), "+f"(c[2]), "+f"(c[3])
        : "r"(a[0]), "r"(a[1]), "r"(a[2]), "r"(a[3]), "r"(b[0]), "r"(b[1]));
}

__device__ __forceinline__ void ldsm4(uint32_t* r, uint32_t addr) {
    asm volatile("ldmatrix.sync.aligned.m8n8.x4.shared.b16 {%0,%1,%2,%3}, [%4];"
                 : "=r"(r[0]), "=r"(r[1]), "=r"(r[2]), "=r"(r[3]) : "r"(addr));
}

__device__ __forceinline__ void cp16(uint32_t dst, const void* src) {
    asm volatile("cp.async.cg.shared.global [%0], [%1], 16;"
                 :: "r"(dst), "l"(src) : "memory");
}
#define CP_COMMIT() asm volatile("cp.async.commit_group;" ::: "memory")

#define SWZ(o) ((o) ^ ((((uint32_t)(o)) >> 3) & 0x70u))

// ---------------- fp16 tensor GEMM (R10 mainloop, untouched) --------------------
// C = A[M,K] * B[N,K]^T.  CTA tile 128x128, BK=64, 3-stage cp.async with early
// burst prefetch, 256 threads, warp tile 32x64.
// EPI 0: C half + row sum/sumsq atomics; z selects (A0,B0,C0,stats0)/(A1,...)
// EPI 1: C half = exp(acc/1024), + rowsum  [QK logits]   (z = batch)
// EPI 2: C f32  = acc / rowsum[row]        [PV output]   (z = batch)
#define TILEB  16384
#define STAGEB 32768
#define GSMEM  (3 * STAGEB)   // 96 KB -> 2 CTAs/SM

__device__ __forceinline__ void load_stage(
    const __half* A, const __half* B, int Kd, int row0, int col0, int kk,
    uint32_t abuf, uint32_t bbuf, int tid)
{
#pragma unroll
    for (int i = 0; i < 4; i++) {
        int ch = tid + i * 256;
        int r = ch >> 3, c = ch & 7;
        cp16(abuf + SWZ(r * 128 + c * 16),
             A + (long long)(row0 + r) * Kd + kk + c * 8);
    }
#pragma unroll
    for (int i = 0; i < 4; i++) {
        int ch = tid + i * 256;
        int r = ch >> 3, c = ch & 7;
        cp16(bbuf + SWZ(r * 128 + c * 16),
             B + (long long)(col0 + r) * Kd + kk + c * 8);
    }
    CP_COMMIT();
}

template <int EPI>
__global__ __launch_bounds__(256, 2)
void gemm_h(const __half* __restrict__ A, const __half* __restrict__ B,
            void* __restrict__ Cv,
            const __half* __restrict__ A1, const __half* __restrict__ B1,
            void* __restrict__ C1,
            float* __restrict__ rowsum, float* __restrict__ stats,
            int M, int N, int Kd,
            long long sA, long long sB, long long sC, long long sR)
{
    extern __shared__ __align__(1024) char smem[];
    if (EPI == 0) {
        if (blockIdx.z) { A = A1; B = B1; Cv = C1; stats += 2 * NROWS; }
    } else {
        A += (long long)blockIdx.z * sA;
        B += (long long)blockIdx.z * sB;
        rowsum += (long long)blockIdx.z * sR;
    }

    const uint32_t sbase = smem_u32(smem);
    const int tid  = threadIdx.x;
    const int warp = tid >> 5;
    const int lane = tid & 31;
    const int gid  = lane >> 2;
    const int tig  = lane & 3;
    const int warp_m = warp & 3;
    const int warp_n = warp >> 2;
    const int row0 = blockIdx.y * 128;
    const int col0 = blockIdx.x * 128;

    const int l7 = lane & 7;
    uint32_t aoff[2], axm[2];
#pragma unroll
    for (int mt = 0; mt < 2; mt++) {
        int row = warp_m * 32 + mt * 16 + ((lane >> 3) & 1) * 8 + l7;
        aoff[mt] = (uint32_t)row * 128;
        axm[mt]  = (uint32_t)(row & 7) * 16;
    }
    const uint32_t aq = (uint32_t)((lane >> 4) & 1) * 16;
    uint32_t boff[4], bxm[4];
#pragma unroll
    for (int p = 0; p < 4; p++) {
        int row = warp_n * 64 + p * 16 + ((lane >> 4) & 1) * 8 + l7;
        boff[p] = (uint32_t)row * 128;
        bxm[p]  = (uint32_t)(row & 7) * 16;
    }
    const uint32_t bq = (uint32_t)((lane >> 3) & 1) * 16;

    float acc[2][8][4];
#pragma unroll
    for (int i = 0; i < 2; i++)
#pragma unroll
        for (int j = 0; j < 8; j++)
#pragma unroll
            for (int l = 0; l < 4; l++) acc[i][j][l] = 0.f;

    const int nst = Kd / 64;

    load_stage(A, B, Kd, row0, col0, 0,  sbase, sbase + TILEB, tid);
    load_stage(A, B, Kd, row0, col0, 64, sbase + STAGEB, sbase + STAGEB + TILEB, tid);

    for (int s = 0; s < nst; s++) {
        if (s + 1 < nst)
            asm volatile("cp.async.wait_group 1;" ::: "memory");
        else
            asm volatile("cp.async.wait_group 0;" ::: "memory");
        __syncthreads();

        // early prefetch of stage s+2 into buffer (s+2)%3 (free after barrier)
        if (s + 2 < nst) {
            int t = s + 2;
            const uint32_t nabuf = sbase + (t % 3) * STAGEB;
            load_stage(A, B, Kd, row0, col0, t * 64, nabuf, nabuf + TILEB, tid);
        }

        const uint32_t abuf = sbase + (s % 3) * STAGEB;
        const uint32_t bbuf = abuf + TILEB;

#pragma unroll
        for (int kg = 0; kg < 4; kg++) {
            uint32_t a[2][4], b[4][4];
#pragma unroll
            for (int mt = 0; mt < 2; mt++)
                ldsm4(a[mt], abuf + aoff[mt] + (((uint32_t)kg * 32 + aq) ^ axm[mt]));
#pragma unroll
            for (int p = 0; p < 4; p++)
                ldsm4(b[p], bbuf + boff[p] + (((uint32_t)kg * 32 + bq) ^ bxm[p]));
#pragma unroll
            for (int mt = 0; mt < 2; mt++)
#pragma unroll
                for (int nt = 0; nt < 8; nt++)
                    mma_fp16(acc[mt][nt], a[mt], &b[nt >> 1][(nt & 1) * 2]);
        }
    }

    // ---- epilogue ----
    if (EPI == 0) {
        __half* C = (__half*)Cv;
        float* ssum = stats;
        float* ssq  = stats + NROWS;
#pragma unroll
        for (int mt = 0; mt < 2; mt++) {
            int r = row0 + warp_m * 32 + mt * 16 + gid;
            float s0 = 0.f, q0 = 0.f, s1 = 0.f, q1 = 0.f;
#pragma unroll
            for (int nt = 0; nt < 8; nt++) {
                int c = col0 + warp_n * 64 + nt * 8 + tig * 2;
                float a0 = acc[mt][nt][0], a1 = acc[mt][nt][1];
                float a2 = acc[mt][nt][2], a3 = acc[mt][nt][3];
                *(__half2*)(C + (long long)r * N + c)       = __floats2half2_rn(a0, a1);
                *(__half2*)(C + (long long)(r + 8) * N + c) = __floats2half2_rn(a2, a3);
                s0 += a0 + a1;  q0 += a0 * a0 + a1 * a1;
                s1 += a2 + a3;  q1 += a2 * a2 + a3 * a3;
            }
            s0 += __shfl_xor_sync(0xffffffffu, s0, 1);
            s0 += __shfl_xor_sync(0xffffffffu, s0, 2);
            q0 += __shfl_xor_sync(0xffffffffu, q0, 1);
            q0 += __shfl_xor_sync(0xffffffffu, q0, 2);
            s1 += __shfl_xor_sync(0xffffffffu, s1, 1);
            s1 += __shfl_xor_sync(0xffffffffu, s1, 2);
            q1 += __shfl_xor_sync(0xffffffffu, q1, 1);
            q1 += __shfl_xor_sync(0xffffffffu, q1, 2);
            if (tig == 0) {
                atomicAdd(&ssum[r], s0);  atomicAdd(&ssq[r], q0);
                atomicAdd(&ssum[r + 8], s1);  atomicAdd(&ssq[r + 8], q1);
            }
        }
    } else if (EPI == 1) {
        __half* C = (__half*)Cv + (long long)blockIdx.z * sC;
        const float sc = 1.4426950408889634f / 1024.0f;  // log2(e)/H
#pragma unroll
        for (int mt = 0; mt < 2; mt++) {
            int r = row0 + warp_m * 32 + mt * 16 + gid;
            float rs0 = 0.f, rs1 = 0.f;
#pragma unroll
            for (int nt = 0; nt < 8; nt++) {
                int c = col0 + warp_n * 64 + nt * 8 + tig * 2;
                float p0 = exp2f(acc[mt][nt][0] * sc);
                float p1 = exp2f(acc[mt][nt][1] * sc);
                float p2 = exp2f(acc[mt][nt][2] * sc);
                float p3 = exp2f(acc[mt][nt][3] * sc);
                *(__half2*)(C + (long long)r * N + c)       = __floats2half2_rn(p0, p1);
                *(__half2*)(C + (long long)(r + 8) * N + c) = __floats2half2_rn(p2, p3);
                rs0 += p0 + p1;
                rs1 += p2 + p3;
            }
            rs0 += __shfl_xor_sync(0xffffffffu, rs0, 1);
            rs0 += __shfl_xor_sync(0xffffffffu, rs0, 2);
            rs1 += __shfl_xor_sync(0xffffffffu, rs1, 1);
            rs1 += __shfl_xor_sync(0xffffffffu, rs1, 2);
            if (tig == 0) {
                atomicAdd(&rowsum[r], rs0);
                atomicAdd(&rowsum[r + 8], rs1);
            }
        }
    } else {
        float* C = (float*)Cv + (long long)blockIdx.z * sC;
#pragma unroll
        for (int mt = 0; mt < 2; mt++) {
            int r = row0 + warp_m * 32 + mt * 16 + gid;
            const float i0 = 1.0f / rowsum[r];
            const float i1 = 1.0f / rowsum[r + 8];
#pragma unroll
            for (int nt = 0; nt < 8; nt++) {
                int c = col0 + warp_n * 64 + nt * 8 + tig * 2;
                *(float2*)(C + (long long)r * N + c) =
                    make_float2(acc[mt][nt][0] * i0, acc[mt][nt][1] * i0);
                *(float2*)(C + (long long)(r + 8) * N + c) =
                    make_float2(acc[mt][nt][2] * i1, acc[mt][nt][3] * i1);
            }
        }
    }
}

// ---------------- pre/aux kernels -----------------------------------------------
// cvt_half with folded aux-clear: blocks [0,20) first zero stats+rowsum slices.
__global__ __launch_bounds__(256) void cvt_half_clear(
    const float4* __restrict__ in, __half2* __restrict__ out, int n4,
    float* __restrict__ stats, float* __restrict__ rowsum)
{
    if (blockIdx.x < 20) {
        int base = blockIdx.x * 4096 + threadIdx.x;   // 20*4096 = 81920 >= 5*16384
#pragma unroll
        for (int i = 0; i < 16; i++) {
            int idx = base + i * 256;
            if (idx < 4 * NROWS) stats[idx] = 0.f;
            else if (idx < 5 * NROWS) rowsum[idx - 4 * NROWS] = 0.f;
        }
    }
    int i = blockIdx.x * 256 + threadIdx.x;
    int stride = gridDim.x * 256;
    for (; i < n4; i += stride) {
        float4 v = in[i];
        out[i * 2 + 0] = __floats2half2_rn(v.x, v.y);
        out[i * 2 + 1] = __floats2half2_rn(v.z, v.w);
    }
}

// Read Y once; emit yh (straight half copy) and yth (transposed half).
__global__ __launch_bounds__(256) void cvt_trans_half(
    const float* __restrict__ in, __half* __restrict__ oh, __half* __restrict__ ot,
    int R, int C, long long sIn, long long sOut)
{
    in += (long long)blockIdx.z * sIn;
    oh += (long long)blockIdx.z * sIn;
    ot += (long long)blockIdx.z * sOut;
    __shared__ float t[32][33];
    const int r0 = blockIdx.y * 32, c0 = blockIdx.x * 32;
    const int tx = threadIdx.x & 31, ty = threadIdx.x >> 5;
#pragma unroll
    for (int i = 0; i < 32; i += 8) {
        float v = in[(long long)(r0 + ty + i) * C + c0 + tx];
        t[ty + i][tx] = v;
        oh[(long long)(r0 + ty + i) * C + c0 + tx] = __float2half_rn(v);
    }
    __syncthreads();
#pragma unroll
    for (int i = 0; i < 32; i += 8)
        ot[(long long)(c0 + ty + i) * R + r0 + tx] = __float2half_rn(t[tx][ty + i]);
}

// Transpose BOTH K and Q in one launch (blockIdx.z selects).
__global__ __launch_bounds__(256) void trans2_half(
    const float* __restrict__ in0, __half* __restrict__ out0,
    const float* __restrict__ in1, __half* __restrict__ out1,
    int R, int C)
{
    const float* in = blockIdx.z ? in1 : in0;
    __half* out = blockIdx.z ? out1 : out0;
    __shared__ float t[32][33];
    const int r0 = blockIdx.y * 32, c0 = blockIdx.x * 32;
    const int tx = threadIdx.x & 31, ty = threadIdx.x >> 5;
#pragma unroll
    for (int i = 0; i < 32; i += 8)
        t[ty + i][tx] = in[(long long)(r0 + ty + i) * C + c0 + tx];
    __syncthreads();
#pragma unroll
    for (int i = 0; i < 32; i += 8)
        out[(long long)(c0 + ty + i) * R + r0 + tx] = __float2half_rn(t[tx][ty + i]);
}

// ---------------- barrier-free layernorm, 4 rows per CTA ------------------------
// 512 threads = 4 warps+... each 128-thread group handles one row; one uint4
// (8 halves) per thread. blockIdx.y selects tensor; blockIdx.x covers 4 rows.
__global__ __launch_bounds__(512) void layernorm2_kernel(
    __half* __restrict__ d0, const float* __restrict__ ga0, const float* __restrict__ be0,
    __half* __restrict__ d1, const float* __restrict__ ga1, const float* __restrict__ be1,
    const float* __restrict__ stats)
{
    const int H = 1024;
    const int rloc = threadIdx.x >> 7;            // 0..3 row within CTA
    const int t    = threadIdx.x & 127;           // 0..127 thread within row
    const int rowi = blockIdx.x * 4 + rloc;

    __half* row = (blockIdx.y ? d1 : d0) + (long long)rowi * H;
    const float* gamma = blockIdx.y ? ga1 : ga0;
    const float* beta  = blockIdx.y ? be1 : be0;
    const float* st = stats + (blockIdx.y ? 2 * NROWS : 0);

    const float s = st[rowi];
    const float q = st[NROWS + rowi];
    const float mu  = s * (1.f / 1024.f);
    const float var = q * (1.f / 1024.f) - mu * mu;
    const float inv = rsqrtf(var + 1e-5f);

    uint4 v = *(uint4*)(row + t * 8);
    __half2 h[4];
    h[0] = *(__half2*)&v.x; h[1] = *(__half2*)&v.y;
    h[2] = *(__half2*)&v.z; h[3] = *(__half2*)&v.w;

    float f[8];
#pragma unroll
    for (int i = 0; i < 4; i++) {
        float2 p = __half22float2(h[i]);
        f[i * 2] = p.x; f[i * 2 + 1] = p.y;
    }

    const int c0 = t * 8;
    float4 g0 = *(const float4*)(gamma + c0);
    float4 g1v = *(const float4*)(gamma + c0 + 4);
    float4 b0 = *(const float4*)(beta + c0);
    float4 b1v = *(const float4*)(beta + c0 + 4);
    const float gg[8] = {g0.x, g0.y, g0.z, g0.w, g1v.x, g1v.y, g1v.z, g1v.w};
    const float bb[8] = {b0.x, b0.y, b0.z, b0.w, b1v.x, b1v.y, b1v.z, b1v.w};

    uint4 o;
    __half2* oh = (__half2*)&o;
#pragma unroll
    for (int i = 0; i < 4; i++) {
        float r0 = (f[i * 2]     - mu) * inv * gg[i * 2]     + bb[i * 2];
        float r1 = (f[i * 2 + 1] - mu) * inv * gg[i * 2 + 1] + bb[i * 2 + 1];
        oh[i] = __floats2half2_rn(r0, r1);
    }
    *(uint4*)(row + t * 8) = o;
}

// ---------------- kernel_launch --------------------------------------------------
extern "C" void kernel_launch(void* const* d_in, const int* in_sizes, int n_in,
                              void* d_out, int out_size)
{
    const float* X  = (const float*)d_in[0];
    const float* Y  = (const float*)d_in[1];
    const float* K  = (const float*)d_in[2];
    const float* Q  = (const float*)d_in[3];
    const float* g1 = (const float*)d_in[4];
    const float* b1 = (const float*)d_in[5];
    const float* g2 = (const float*)d_in[6];
    const float* b2 = (const float*)d_in[7];
    float* out = (float*)d_out;

    __half *xh, *yh, *kth, *qth, *yth, *keysh, *queriesh, *alphah;
    float *rowsum, *stats;
    cudaGetSymbolAddress((void**)&xh,       g_xh);
    cudaGetSymbolAddress((void**)&yh,       g_yh);
    cudaGetSymbolAddress((void**)&kth,      g_kth);
    cudaGetSymbolAddress((void**)&qth,      g_qth);
    cudaGetSymbolAddress((void**)&yth,      g_yth);
    cudaGetSymbolAddress((void**)&keysh,    g_keysh);
    cudaGetSymbolAddress((void**)&queriesh, g_queriesh);
    cudaGetSymbolAddress((void**)&alphah,   g_alphah);
    cudaGetSymbolAddress((void**)&rowsum,   g_rowsum);
    cudaGetSymbolAddress((void**)&stats,    g_stats);

    cudaFuncSetAttribute(gemm_h<0>, cudaFuncAttributeMaxDynamicSharedMemorySize, GSMEM);
    cudaFuncSetAttribute(gemm_h<1>, cudaFuncAttributeMaxDynamicSharedMemorySize, GSMEM);
    cudaFuncSetAttribute(gemm_h<2>, cudaFuncAttributeMaxDynamicSharedMemorySize, GSMEM);

    const int B = 8, S = 2048, F = 1024, H = 1024;
    const long long nXY = (long long)B * S * F;
    const long long sQK = (long long)S * H;
    const long long sAL = (long long)S * S;
    const long long sY  = (long long)S * F;
    const long long sYT = (long long)F * S;

    // 1) X convert (+ folded stats/rowsum clear); Y -> yh+yth; K,Q transposes
    cvt_half_clear<<<2048, 256>>>((const float4*)X, (__half2*)xh, (int)(nXY / 4),
                                  stats, rowsum);
    cvt_trans_half<<<dim3(F / 32, S / 32, B), 256>>>(Y, yh, yth, S, F, sY, sYT);
    trans2_half<<<dim3(H / 32, F / 32, 2), 256>>>(K, kth, Q, qth, F, H);

    // 2) both projections in ONE launch (z selects pair); epilogue emits LN stats
    gemm_h<0><<<dim3(H / 128, (B * S) / 128, 2), 256, GSMEM>>>(
        yh, kth, keysh, xh, qth, queriesh, nullptr, stats,
        B * S, H, F, 0, 0, 0, 0);

    // 3) barrier-free layernorms, 4 rows per CTA
    layernorm2_kernel<<<dim3(B * S / 4, 2), 512>>>(keysh, g1, b1, queriesh, g2, b2, stats);

    // 4) QK logits + fused exp + row sums: alphah = exp(q.k/H)
    gemm_h<1><<<dim3(S / 128, S / 128, B), 256, GSMEM>>>(
        queriesh, keysh, alphah, nullptr, nullptr, nullptr, rowsum, nullptr,
        S, S, H, sQK, sQK, sAL, S);

    // 5) PV + fused division: out = (alphah @ yth^T) / rowsum
    gemm_h<2><<<dim3(F / 128, S / 128, B), 256, GSMEM>>>(
        alphah, yth, out, nullptr, nullptr, nullptr, rowsum, nullptr,
        S, F, S, sAL, sYT, sY, S);
}